// round 5
// baseline (speedup 1.0000x reference)
#include <cuda_runtime.h>
#include <cstdint>

#define U64 unsigned long long

// ---------------- scratch (static device memory; no allocation) ----------------
__device__ float  g_A [128u*1024u*96u];     // A[x][ij][c]: c<32 Wr, 32..63 Wi, 64..95 Wr+Wi   (50 MB)
__device__ float  g_B [128u*3u*32u*2048u];  // B[x][plane][c][n2]: planes dxr, dxi, dxr+dxi    (100 MB)
__device__ float  g_Mr[128u*2048u*1024u];   // Mr[x][n2][ij]   (1.07 GB)
__device__ float  g_Mi[128u*2048u*1024u];   // Mi[x][n2][ij]   (1.07 GB)
__device__ float2 g_Hf[128u*256u*256u];     // Hf[x][b*32+i][t]  (67 MB)
__device__ float2 g_Z0f[128u*256u];         // Z0f[x][b*32+i]
__device__ float2 g_Zs[256u*256u*128u];     // Zs[b*32+i][t][x]  (67 MB)
__device__ float  g_Fz[256u*128u];
__device__ float  g_Gz[256u*8u*128u];

// ---------------- helpers ----------------
__device__ __forceinline__ U64 pk2(float lo, float hi){
    U64 r; asm("mov.b64 %0, {%1, %2};" : "=l"(r) : "f"(lo), "f"(hi)); return r;
}
__device__ __forceinline__ float2 upk2(U64 v){
    float lo, hi; asm("mov.b64 {%0, %1}, %2;" : "=f"(lo), "=f"(hi) : "l"(v));
    return make_float2(lo, hi);
}
#define FMA2(acc, a, b) asm("fma.rn.f32x2 %0, %1, %2, %0;" : "+l"(acc) : "l"(a), "l"(b))

__device__ __forceinline__ int rev7(int v){ return (int)(__brev((unsigned)v) >> 25); }

__device__ __forceinline__ void build_tw(float2* tw, int tid, float sign){
    if (tid < 64){
        float ang = sign * 6.28318530717958647692f * (float)tid * (1.0f/128.0f);
        float s, c; __sincosf(ang, &s, &c);
        tw[tid] = make_float2(c, s);
    }
}

__device__ __forceinline__ void fft_inplace(float2* buf, int nt, const float2* tw,
                                            int tid, int nth){
    #pragma unroll
    for (int s = 0; s < 7; s++){
        int half = 1 << s;
        int nbf = nt << 6;
        for (int idx = tid; idx < nbf; idx += nth){
            int q   = idx & 63;
            int row = idx >> 6;
            int p   = q & (half - 1);
            int g   = q >> s;
            int i0  = row * 128 + g * (half << 1) + p;
            float2 a = buf[i0], b = buf[i0 + half];
            float2 w = tw[p << (6 - s)];
            float2 t = make_float2(w.x*b.x - w.y*b.y, w.x*b.y + w.y*b.x);
            buf[i0]        = make_float2(a.x + t.x, a.y + t.y);
            buf[i0 + half] = make_float2(a.x - t.x, a.y - t.y);
        }
        __syncthreads();
    }
}

// ---------------- K0: build A matrix (W reshaped + Gauss sum plane) ----------------
// grid (128, 32) = (x, i), 1024 threads = c*32 + j
__global__ void k0_amat(const float* __restrict__ Wr, const float* __restrict__ Wi){
    __shared__ float2 s[32][33];
    int x = blockIdx.x, i = blockIdx.y;
    int tid = threadIdx.x;
    int c = tid >> 5, j = tid & 31;
    size_t base = (((size_t)(x*32 + i))*32 + c)*32 + j;
    s[c][j] = make_float2(Wr[base], Wi[base]);
    __syncthreads();
    int j2 = tid >> 5, c2 = tid & 31;
    float2 w = s[c2][j2];
    size_t ab = ((size_t)(x*1024 + i*32 + j2))*96;
    g_A[ab + c2]      = w.x;
    g_A[ab + 32 + c2] = w.y;
    g_A[ab + 64 + c2] = w.x + w.y;
}

// ---------------- K1 ----------------
__global__ void k1_proj(const float* __restrict__ z0, const float* __restrict__ A,
                        const float* __restrict__ Gw){
    int bi = blockIdx.x; int b = bi >> 5, i = bi & 31;
    int x = threadIdx.x;
    float zv[32];
    #pragma unroll
    for (int h = 0; h < 32; h++) zv[h] = z0[((size_t)(b*32 + h))*128 + x];
    float f = 0.f;
    #pragma unroll
    for (int h = 0; h < 32; h++) f += A[i*32 + h] * zv[h];
    g_Fz[bi*128 + x] = f;
    for (int fi = 0; fi < 8; fi++){
        float g = 0.f;
        #pragma unroll
        for (int h = 0; h < 32; h++) g += Gw[(i*8 + fi)*32 + h] * zv[h];
        g_Gz[(bi*8 + fi)*128 + x] = g;
    }
}

// ---------------- K2b: fftshift(fft_x(z0)) ----------------
__global__ void k2b_z0fft(const float* __restrict__ z0){
    __shared__ float2 buf[128];
    __shared__ float2 tw[64];
    int bi = blockIdx.x;
    int tid = threadIdx.x;
    build_tw(tw, tid, -1.f);
    buf[rev7(tid)] = make_float2(z0[(size_t)bi*128 + tid], 0.f);
    __syncthreads();
    fft_inplace(buf, 1, tw, tid, 128);
    int xs = (tid + 64) & 127;
    g_Z0f[xs*256 + bi] = buf[tid];
}

// ---------------- K2: Hu + FFT_x + shift -> g_Hf ----------------
__global__ void k2_hufft(const float* __restrict__ xi){
    __shared__ float2 buf[16*128];
    __shared__ float  Gl[8*128];
    __shared__ float  Fl[128];
    __shared__ float2 tw[64];
    int bi = blockIdx.x; int b = bi >> 5;
    int t0 = blockIdx.y * 16;
    int tid = threadIdx.x;
    build_tw(tw, tid, -1.f);
    if (tid < 128) Fl[tid] = g_Fz[bi*128 + tid];
    for (int idx = tid; idx < 1024; idx += 256) Gl[idx] = g_Gz[(size_t)bi*1024 + idx];
    __syncthreads();
    #pragma unroll
    for (int k = 0; k < 8; k++){
        int idx = tid + k*256;
        int tt = idx & 15, x = idx >> 4;
        float hu = Fl[x];
        #pragma unroll
        for (int f = 0; f < 8; f++)
            hu += Gl[f*128 + x] * xi[((size_t)(b*8 + f)*128 + x)*256 + t0 + tt];
        buf[tt*128 + rev7(x)] = make_float2(hu, 0.f);
    }
    __syncthreads();
    fft_inplace(buf, 16, tw, tid, 256);
    #pragma unroll
    for (int k = 0; k < 8; k++){
        int idx = tid + k*256;
        int tt = idx & 15, xk = idx >> 4;
        int xs = (xk + 64) & 127;
        g_Hf[(size_t)xs*65536 + (size_t)bi*256 + t0 + tt] = buf[tt*128 + xk];
    }
}

// ---------------- K2c: build B (dx planes) ----------------
// grid (128, 255) = (x, t); 256 threads = b*32 + c
__global__ void k2c_bmat(){
    int x = blockIdx.x, t = blockIdx.y;
    int tid = threadIdx.x;
    int b = tid >> 5, c = tid & 31;
    const float2* hp = g_Hf + (size_t)x*65536 + (size_t)(b*32 + c)*256 + t;
    float2 h0 = hp[0], h1 = hp[1];
    float dr = h1.x - h0.x, di = h1.y - h0.y;
    int n2 = t*8 + b;
    float* Bx = g_B + (size_t)x*3u*32u*2048u;
    Bx[(size_t)c*2048 + n2]              = dr;
    Bx[65536u + (size_t)c*2048 + n2]     = di;
    Bx[131072u + (size_t)c*2048 + n2]    = dr + di;
}

// ---------------- KA: batched GEMM  M_t = contract(W, dx)  (Gauss 3-mult) ----------------
// grid (nt=32, mt=16, x=128); 256 threads (16 n-thr × 16 m-thr); micro 4m×4n
__global__ __launch_bounds__(256, 2) void kA_gemm(){
    __shared__ float At[96][64];      // [c][m]  24 KB
    __shared__ float Bs[3][32][64];   // [plane][c][n]  24 KB
    int nt = blockIdx.x, mt = blockIdx.y, x = blockIdx.z;
    int tid = threadIdx.x;

    // load A tile (64 m-rows × 96 c), transposed into At[c][m]
    const float* Ag = g_A + ((size_t)(x*1024 + mt*64))*96;
    {
        int mrow = tid >> 2;           // 0..63
        int cb   = (tid & 3)*4;        // 0,4,8,12
        #pragma unroll
        for (int r = 0; r < 6; r++){
            int c = cb + r*16;         // covers 0..95
            float4 v = *(const float4*)(Ag + (size_t)mrow*96 + c);
            At[c+0][mrow] = v.x; At[c+1][mrow] = v.y;
            At[c+2][mrow] = v.z; At[c+3][mrow] = v.w;
        }
    }
    // load B tile: 96 rows (3 planes × 32 c) × 64 n
    {
        const float* Bg = g_B + (size_t)x*3u*32u*2048u + nt*64;
        #pragma unroll
        for (int r = 0; r < 6; r++){
            int idx = tid + r*256;
            int row = idx >> 4;        // 0..95
            int f4  = (idx & 15)*4;
            float4 v = *(const float4*)(Bg + (size_t)row*2048 + f4);
            *(float4*)&Bs[0][0][0 + (size_t)row*64 + f4] = v;
        }
    }
    __syncthreads();

    int txx = tid & 15, tyy = tid >> 4;
    int m0 = tyy*4, n0 = txx*4;
    U64 P[4][2] = {}, Q[4][2] = {}, S[4][2] = {};
    #pragma unroll
    for (int k = 0; k < 32; k++){
        float4 ar = *(const float4*)&At[k][m0];
        float4 ai = *(const float4*)&At[32+k][m0];
        float4 as = *(const float4*)&At[64+k][m0];
        float4 br4 = *(const float4*)&Bs[0][k][n0];
        float4 bi4 = *(const float4*)&Bs[1][k][n0];
        float4 bs4 = *(const float4*)&Bs[2][k][n0];
        U64 br0 = pk2(br4.x, br4.y), br1 = pk2(br4.z, br4.w);
        U64 bi0 = pk2(bi4.x, bi4.y), bi1 = pk2(bi4.z, bi4.w);
        U64 bs0 = pk2(bs4.x, bs4.y), bs1 = pk2(bs4.z, bs4.w);
        float arr[4] = {ar.x, ar.y, ar.z, ar.w};
        float aii[4] = {ai.x, ai.y, ai.z, ai.w};
        float ass[4] = {as.x, as.y, as.z, as.w};
        #pragma unroll
        for (int mi = 0; mi < 4; mi++){
            U64 adr = pk2(arr[mi], arr[mi]);
            U64 adi = pk2(aii[mi], aii[mi]);
            U64 ads = pk2(ass[mi], ass[mi]);
            FMA2(P[mi][0], adr, br0); FMA2(P[mi][1], adr, br1);
            FMA2(Q[mi][0], adi, bi0); FMA2(Q[mi][1], adi, bi1);
            FMA2(S[mi][0], ads, bs0); FMA2(S[mi][1], ads, bs1);
        }
    }

    // epilogue: Mr = P - Q ; Mi = S - P - Q ; write per-n rows of 4 m
    #pragma unroll
    for (int nn = 0; nn < 4; nn++){
        int hp = nn >> 1, ho = nn & 1;
        float4 vr, vi;
        float* pr = (float*)&vr; float* pi = (float*)&vi;
        #pragma unroll
        for (int mi = 0; mi < 4; mi++){
            float2 pe = upk2(P[mi][hp]);
            float2 qe = upk2(Q[mi][hp]);
            float2 se = upk2(S[mi][hp]);
            float p = ho ? pe.y : pe.x;
            float q = ho ? qe.y : qe.x;
            float s = ho ? se.y : se.x;
            pr[mi] = p - q;
            pi[mi] = s - p - q;
        }
        size_t row = ((size_t)x*2048 + (size_t)(nt*64 + n0 + nn))*1024 + mt*64 + m0;
        *(float4*)(g_Mr + row) = vr;
        *(float4*)(g_Mi + row) = vi;
    }
}

// ---------------- K3b: lightweight sequential scan  z <- z + M_t z ----------------
// grid 128 (x), 512 threads = (b(8), i(32), h(2)); M prefetched 1 step (ping-pong regs)
struct MRegs { float4 r[4]; float4 i[4]; };

__device__ __forceinline__ void k3b_load(MRegs& m, size_t off){
    #pragma unroll
    for (int q = 0; q < 4; q++){
        m.r[q] = *(const float4*)(g_Mr + off + q*4);
        m.i[q] = *(const float4*)(g_Mi + off + q*4);
    }
}

__device__ __forceinline__ void k3b_body(int t, const MRegs& cm, MRegs& nm,
                                         size_t bo, int x, int b, int i, int h,
                                         float (*zr)[8][32], float (*zi)[8][32],
                                         float& zrr, float& zir, bool last){
    // prefetch M for t+1
    if (!last){
        size_t off = bo + (size_t)(t + 1)*8192;
        k3b_load(nm, off);
    }
    // store z_t
    if (h == 0)
        g_Zs[(size_t)(b*32 + i)*32768 + (size_t)t*128 + x] = make_float2(zrr, zir);
    int cb = t & 1;
    const float4* zrp = (const float4*)&zr[cb][b][h*16];
    const float4* zip = (const float4*)&zi[cb][b][h*16];
    float s1 = 0.f, s2 = 0.f, s3 = 0.f, s4 = 0.f;
    #pragma unroll
    for (int q = 0; q < 4; q++){
        float4 zr4 = zrp[q], zi4 = zip[q];
        float4 mr4 = cm.r[q], mi4 = cm.i[q];
        s1 += mr4.x*zr4.x + mr4.y*zr4.y + mr4.z*zr4.z + mr4.w*zr4.w;
        s2 += mi4.x*zi4.x + mi4.y*zi4.y + mi4.z*zi4.z + mi4.w*zi4.w;
        s3 += mr4.x*zi4.x + mr4.y*zi4.y + mr4.z*zi4.z + mr4.w*zi4.w;
        s4 += mi4.x*zr4.x + mi4.y*zr4.y + mi4.z*zr4.z + mi4.w*zr4.w;
    }
    float dzr = s1 - s2;
    float dzi = s3 + s4;
    dzr += __shfl_xor_sync(0xffffffffu, dzr, 1);
    dzi += __shfl_xor_sync(0xffffffffu, dzi, 1);
    if (h == 0){
        zrr += dzr; zir += dzi;
        zr[cb ^ 1][b][i] = zrr;
        zi[cb ^ 1][b][i] = zir;
    }
    __syncthreads();
}

__global__ __launch_bounds__(512, 1) void k3b_scan(){
    __shared__ float zr[2][8][32];
    __shared__ float zi[2][8][32];
    int x = blockIdx.x, tid = threadIdx.x;
    int b = tid >> 6, i = (tid >> 1) & 31, h = tid & 1;
    if (tid < 256){
        float2 z = g_Z0f[x*256 + tid];
        zr[0][tid >> 5][tid & 31] = z.x;
        zi[0][tid >> 5][tid & 31] = z.y;
    }
    __syncthreads();
    float zrr = 0.f, zir = 0.f;
    if (h == 0){ zrr = zr[0][b][i]; zir = zi[0][b][i]; }

    size_t bo = ((size_t)x*2048 + b)*1024 + i*32 + h*16;
    MRegs mA, mB;
    k3b_load(mA, bo);   // t = 0

    for (int t = 0; t < 254; t += 2){
        k3b_body(t,     mA, mB, bo, x, b, i, h, zr, zi, zrr, zir, false);
        k3b_body(t + 1, mB, mA, bo, x, b, i, h, zr, zi, zrr, zir, false);
    }
    k3b_body(254, mA, mB, bo, x, b, i, h, zr, zi, zrr, zir, true);

    if (h == 0)
        g_Zs[(size_t)(b*32 + i)*32768 + (size_t)255*128 + x] = make_float2(zrr, zir);
}

// ---------------- K4: ifftshift + IFFT_x + real part -> out ----------------
__global__ void k4_ifft(float* __restrict__ out){
    __shared__ float2 buf[16*128];
    __shared__ float2 tw[64];
    int bi = blockIdx.x;
    int t0 = blockIdx.y * 16;
    int tid = threadIdx.x;
    build_tw(tw, tid, +1.f);
    #pragma unroll
    for (int k = 0; k < 8; k++){
        int idx = tid + k*256;
        int m = idx & 127, tt = idx >> 7;
        float2 v = g_Zs[(size_t)bi*32768 + (size_t)(t0 + tt)*128 + ((m + 64) & 127)];
        buf[tt*128 + rev7(m)] = v;
    }
    __syncthreads();
    fft_inplace(buf, 16, tw, tid, 256);
    #pragma unroll
    for (int k = 0; k < 8; k++){
        int idx = tid + k*256;
        int tt = idx & 15, n = idx >> 4;
        out[((size_t)bi*128 + n)*256 + t0 + tt] = buf[tt*128 + n].x * (1.0f/128.0f);
    }
}

// ---------------- launch ----------------
extern "C" void kernel_launch(void* const* d_in, const int* in_sizes, int n_in,
                              void* d_out, int out_size){
    const float* z0 = (const float*)d_in[0];
    const float* xi = (const float*)d_in[1];
    const float* A  = (const float*)d_in[2];
    const float* Gw = (const float*)d_in[3];
    const float* Wr = (const float*)d_in[4];
    const float* Wi = (const float*)d_in[5];
    float* out = (float*)d_out;

    k0_amat<<<dim3(128, 32), 1024>>>(Wr, Wi);
    k1_proj<<<256, 128>>>(z0, A, Gw);
    k2b_z0fft<<<256, 128>>>(z0);
    k2_hufft<<<dim3(256, 16), 256>>>(xi);
    k2c_bmat<<<dim3(128, 255), 256>>>();
    kA_gemm<<<dim3(32, 16, 128), 256>>>();
    k3b_scan<<<128, 512>>>();
    k4_ifft<<<dim3(256, 16), 256>>>(out);
    (void)in_sizes; (void)n_in; (void)out_size;
}